// round 7
// baseline (speedup 1.0000x reference)
#include <cuda_runtime.h>

// EOQLinear int4-GEMV, N=K=8192, qblock=128. x/scales/out are fp32 (harness
// promotes fp16). packed_w: int32 in [0,256): lo nibble -> even k, hi -> odd k,
// offset-8. HBM-bound: 128MB of W read once.
//
// R7: rows-inner loop + explicit depth-4 load pipeline. Each thread owns 2
// qblocks (xr[8] per chunk), accumulates 16 independent row sums, keeping >=4
// LDG.128 in flight per thread within the 64-reg / 2-CTA (32 warp/SM) budget.

constexpr int KDIM   = 8192;
constexpr int WORDS4 = KDIM / 8;  // 1024 int4 (16B) per row
constexpr int QBLK   = 64;        // quant blocks per row
constexpr int TPB    = 512;
constexpr int RPB    = 16;        // rows per CTA (one per warp in the reduction)
constexpr int PF     = 4;         // prefetch depth (rows)

// (w & 0xF) | 0x4B000000 is exactly float(2^23 + lo); subtract 2^23+8 -> exact lo-8.
__device__ __forceinline__ float dec_lo(int w) {
    return __int_as_float((w & 0xF) | 0x4B000000) - 8388616.0f;
}
__device__ __forceinline__ float dec_hi(int w) {
    return __int_as_float(((w >> 4) & 0xF) | 0x4B000000) - 8388616.0f;
}

__global__ __launch_bounds__(TPB, 2)
void q4_gemv_kernel(const float* __restrict__ x,       // [8192]
                    const int4*  __restrict__ wq,      // [8192, 1024] int4 view
                    const float* __restrict__ scales,  // [8192, 64]
                    float* __restrict__ out)           // [8192]
{
    __shared__ float red[RPB][TPB];

    const int t = threadIdx.x;
    const int g = t >> 4;   // 0..31: owns qblocks 2g, 2g+1
    const int s = t & 15;   // word-quad position inside a qblock
    const int row0 = blockIdx.x * RPB;

    float racc[RPB];
#pragma unroll
    for (int r = 0; r < RPB; r++) racc[r] = 0.0f;

#pragma unroll
    for (int i = 0; i < 2; i++) {
        const int qb = 2 * g + i;

        // x slice for this qblock chunk: 8 floats, loop-invariant across rows.
        float xr[8];
        {
            const float4 a = *reinterpret_cast<const float4*>(x + qb * 128 + s * 8);
            const float4 b = *reinterpret_cast<const float4*>(x + qb * 128 + s * 8 + 4);
            xr[0] = a.x; xr[1] = a.y; xr[2] = a.z; xr[3] = a.w;
            xr[4] = b.x; xr[5] = b.y; xr[6] = b.z; xr[7] = b.w;
        }

        const int4*  wp = wq + (long)row0 * WORDS4 + qb * 16 + s;  // stride WORDS4/row
        const float* sp = scales + (long)row0 * QBLK + qb;          // stride QBLK/row

        // Fill the depth-4 pipeline.
        int4  wbuf[PF];
        float cbuf[PF];
#pragma unroll
        for (int r = 0; r < PF; r++) {
            wbuf[r] = __ldcs(wp + r * WORDS4);
            cbuf[r] = __ldg(sp + r * QBLK);
        }

#pragma unroll
        for (int r = 0; r < RPB; r++) {
            const int4  wv = wbuf[r & (PF - 1)];
            const float cc = cbuf[r & (PF - 1)];
            if (r + PF < RPB) {
                wbuf[r & (PF - 1)] = __ldcs(wp + (r + PF) * WORDS4);
                cbuf[r & (PF - 1)] = __ldg(sp + (r + PF) * QBLK);
            }
            float p = 0.0f;
            p = fmaf(dec_lo(wv.x), xr[0], p);
            p = fmaf(dec_hi(wv.x), xr[1], p);
            p = fmaf(dec_lo(wv.y), xr[2], p);
            p = fmaf(dec_hi(wv.y), xr[3], p);
            p = fmaf(dec_lo(wv.z), xr[4], p);
            p = fmaf(dec_hi(wv.z), xr[5], p);
            p = fmaf(dec_lo(wv.w), xr[6], p);
            p = fmaf(dec_hi(wv.w), xr[7], p);
            // One multiply by the block scale per qblock (factored-scale form).
            racc[r] = fmaf(p, cc, racc[r]);
        }
    }

#pragma unroll
    for (int r = 0; r < RPB; r++) red[r][t] = racc[r];
    __syncthreads();

    // Warp w reduces row (row0 + w) across the 512 threads.
    const int wid = t >> 5, lane = t & 31;
    float v = 0.0f;
#pragma unroll
    for (int k = 0; k < TPB / 32; k++) v += red[wid][lane + 32 * k];
#pragma unroll
    for (int o = 16; o > 0; o >>= 1) v += __shfl_xor_sync(0xFFFFFFFFu, v, o);
    if (lane == 0) out[row0 + wid] = v;
}

extern "C" void kernel_launch(void* const* d_in, const int* in_sizes, int n_in,
                              void* d_out, int out_size) {
    const float* x      = (const float*)d_in[0];
    const int4*  wq     = (const int4*)d_in[1];
    const float* scales = (const float*)d_in[2];
    // d_in[3] = qblock_size (128), compile-time constant here.
    float* out = (float*)d_out;

    const int n_rows = out_size;  // 8192
    q4_gemv_kernel<<<n_rows / RPB, TPB>>>(x, wq, scales, out);
}